// round 1
// baseline (speedup 1.0000x reference)
#include <cuda_runtime.h>

// HGT_DNF conjunction layer, collapsed formulation.
// out[b,o] = sum_r ( P[b,r]*max(w[r,o],0) + M[b,r]*min(w[r,o],0) )
//          + max_r ( Vd[b,r]*|w[r,o]| )
// where, aggregating over n with idx[n]==r:
//   A = sum mask(x)*x, U = sum |x|, V = max |x|
//   P = A - DELTA*U, M = A + DELTA*U, Vd = DELTA*V
// This is exactly  x*mask @ W + DELTA*(max|xW| - sum|xW|)  with W = weights[idx].

#define BB 4096
#define NPRED 106
#define RR 54
#define OO 1024
#define DELTA_C 0.01f

#define TB 64      // batch-rows per block tile
#define TO 64      // out-cols per block tile
#define THREADS 256

__device__ float g_P[RR * BB];
__device__ float g_M[RR * BB];
__device__ float g_V[RR * BB];

// ---------------- Kernel 1: per-batch-row aggregation ----------------
// grid = BB/128, block = 128; one thread per batch row.
__global__ void __launch_bounds__(128) k_rows(const float* __restrict__ x,
                                              const int* __restrict__ idx) {
    __shared__ int s_start[RR + 1];
    __shared__ int s_fill[RR];
    __shared__ int s_order[NPRED];

    int tid = threadIdx.x;
    if (tid < RR) { s_start[tid + 1] = 0; s_fill[tid] = 0; }
    if (tid == 0) s_start[0] = 0;
    __syncthreads();
    if (tid < NPRED) atomicAdd(&s_start[idx[tid] + 1], 1);
    __syncthreads();
    if (tid == 0) {
        for (int r = 0; r < RR; r++) s_start[r + 1] += s_start[r];
    }
    __syncthreads();
    if (tid < NPRED) {
        int r = idx[tid];
        int p = atomicAdd(&s_fill[r], 1);
        s_order[s_start[r] + p] = tid;
    }
    __syncthreads();

    int b = blockIdx.x * 128 + tid;
    const float* xr = x + (long)b * NPRED;

    for (int r = 0; r < RR; r++) {
        float A = 0.0f, U = 0.0f, V = 0.0f;
        int e0 = s_start[r], e1 = s_start[r + 1];
        for (int e = e0; e < e1; e++) {
            int n = s_order[e];
            float xv = __ldg(&xr[n]);
            float a = (xv >= -1.0f) ? xv : 0.0f;
            float ax = fabsf(xv);
            A += a;
            U += ax;
            V = fmaxf(V, ax);
        }
        g_P[r * BB + b] = A - DELTA_C * U;
        g_M[r * BB + b] = A + DELTA_C * U;
        g_V[r * BB + b] = DELTA_C * V;
    }
}

// ---------------- Kernel 2: main fused GEMM + max ----------------
// grid = (OO/TO, BB/TB), block = 256 (16 col-groups x 16 row-groups),
// each thread computes a 4x4 micro-tile.
__global__ void __launch_bounds__(THREADS, 2)
k_main(const float* __restrict__ w, float* __restrict__ out) {
    extern __shared__ float sm[];
    float* sP  = sm;                 // [RR][TB]
    float* sM  = sP  + RR * TB;
    float* sV  = sM  + RR * TB;
    float* swp = sV  + RR * TB;      // [RR][TO]
    float* swm = swp + RR * TO;
    float* saw = swm + RR * TO;

    int tid = threadIdx.x;
    int b0 = blockIdx.y * TB;
    int o0 = blockIdx.x * TO;

    // Stage row aggregates (coalesced: consecutive b within each r).
    for (int i = tid; i < RR * TB; i += THREADS) {
        int r = i / TB, b = i % TB;
        int g = r * BB + b0 + b;
        sP[i] = g_P[g];
        sM[i] = g_M[g];
        sV[i] = g_V[g];
    }
    // Stage weight tile and derived forms.
    for (int i = tid; i < RR * TO; i += THREADS) {
        int r = i / TO, o = i % TO;
        float wv = __ldg(&w[r * OO + o0 + o]);
        swp[i] = fmaxf(wv, 0.0f);
        swm[i] = fminf(wv, 0.0f);
        saw[i] = fabsf(wv);
    }
    __syncthreads();

    int tx = tid & 15;        // col group
    int ty = tid >> 4;        // row group
    int ro = ty * 4;
    int co = tx * 4;

    float acc[4][4];
    float mx[4][4];
#pragma unroll
    for (int i = 0; i < 4; i++)
#pragma unroll
        for (int j = 0; j < 4; j++) { acc[i][j] = 0.0f; mx[i][j] = 0.0f; }

#pragma unroll 3
    for (int r = 0; r < RR; r++) {
        float4 Pv4 = *(const float4*)&sP [r * TB + ro];
        float4 Mv4 = *(const float4*)&sM [r * TB + ro];
        float4 Vv4 = *(const float4*)&sV [r * TB + ro];
        float4 wp4 = *(const float4*)&swp[r * TO + co];
        float4 wm4 = *(const float4*)&swm[r * TO + co];
        float4 aw4 = *(const float4*)&saw[r * TO + co];
        float Pv[4] = {Pv4.x, Pv4.y, Pv4.z, Pv4.w};
        float Mv[4] = {Mv4.x, Mv4.y, Mv4.z, Mv4.w};
        float Vv[4] = {Vv4.x, Vv4.y, Vv4.z, Vv4.w};
        float wp[4] = {wp4.x, wp4.y, wp4.z, wp4.w};
        float wm[4] = {wm4.x, wm4.y, wm4.z, wm4.w};
        float aw[4] = {aw4.x, aw4.y, aw4.z, aw4.w};
#pragma unroll
        for (int i = 0; i < 4; i++) {
#pragma unroll
            for (int j = 0; j < 4; j++) {
                acc[i][j] = fmaf(Pv[i], wp[j], acc[i][j]);
                acc[i][j] = fmaf(Mv[i], wm[j], acc[i][j]);
                float t = Vv[i] * aw[j];
                mx[i][j] = fmaxf(mx[i][j], t);
            }
        }
    }

    // Epilogue: out = acc + mx  (V already scaled by DELTA). float4 stores.
#pragma unroll
    for (int i = 0; i < 4; i++) {
        float4 res;
        res.x = acc[i][0] + mx[i][0];
        res.y = acc[i][1] + mx[i][1];
        res.z = acc[i][2] + mx[i][2];
        res.w = acc[i][3] + mx[i][3];
        *(float4*)&out[(long)(b0 + ro + i) * OO + o0 + co] = res;
    }
}

extern "C" void kernel_launch(void* const* d_in, const int* in_sizes, int n_in,
                              void* d_out, int out_size) {
    const float* x   = (const float*)d_in[0];   // [4096, 106] f32
    const float* w   = (const float*)d_in[1];   // [54, 1024] f32
    const int*   idx = (const int*)d_in[2];     // [106] i32
    float* out = (float*)d_out;                 // [4096, 1024] f32

    const int smem = (3 * RR * TB + 3 * RR * TO) * (int)sizeof(float);  // 82944 B
    cudaFuncSetAttribute(k_main, cudaFuncAttributeMaxDynamicSharedMemorySize, smem);

    k_rows<<<BB / 128, 128>>>(x, idx);
    dim3 grid(OO / TO, BB / TB);
    k_main<<<grid, THREADS, smem>>>(w, out);
}